// round 6
// baseline (speedup 1.0000x reference)
#include <cuda_runtime.h>
#include <cstdint>

// Problem constants (fixed shapes)
#define BB    16
#define RS    128
#define TT    128          // T = COLS * C, C == 1
#define HH    32
#define GG    96           // 3*H
#define NV    258          // vocab
#define NTOK  (BB*RS*TT)   // 262144
#define WSLOT (GG*HH)      // 3072 floats per transposed weight matrix

// -------- device scratch (static globals: no allocation) --------
__device__ float g_embW[NV*GG];          // W_ih0[:, :64] @ embed^T  -> [258][96]
__device__ float g_W[6*WSLOT];           // 6 transposed matrices [32][96] k-major:
                                         // 0:M (Wih0@Wh2e) 1:whh0 2:wih1 3:whh1 4:wih2 5:whh2
__device__ float g_base[GG];             // b_ih0 + Wih0@b_h2e
__device__ float g_w64[GG];              // Wih0[:,64] (row-pos column)
__device__ float g_h[(size_t)NTOK*HH];   // top-layer GRU outputs [B][R][T][H]
__device__ int   g_prog[RS*BB];          // progress counters, prog[r*16+b] = #t done

// -------- helpers --------
__device__ __forceinline__ float sigf(float x)   { return __fdividef(1.0f, 1.0f + __expf(-x)); }
__device__ __forceinline__ float tanh_f(float x) { return __fdividef(2.0f, 1.0f + __expf(-2.0f*x)) - 1.0f; }

// -------- kernel 0: zero progress flags (needed every launch/replay) --------
__global__ void zero_prog_kernel() {
    int i = blockIdx.x*blockDim.x + threadIdx.x;
    if (i < RS*BB) g_prog[i] = 0;
}

// -------- kernel 1: precompute folded weights --------
__global__ void precompute_kernel(
    const float* __restrict__ emb,   // [258][64]
    const float* __restrict__ wih0,  // [96][65]
    const float* __restrict__ bih0,  // [96]
    const float* __restrict__ wh2e,  // [65][32]
    const float* __restrict__ bh2e,  // [65]
    const float* __restrict__ whh0,  // [96][32]
    const float* __restrict__ wih1,  // [96][32]
    const float* __restrict__ whh1,
    const float* __restrict__ wih2,
    const float* __restrict__ whh2)
{
    int g = threadIdx.x;     // 0..95
    int blk = blockIdx.x;
    if (blk < NV) {
        float s = 0.f;
        #pragma unroll
        for (int e = 0; e < 64; ++e) s = fmaf(wih0[g*65+e], emb[blk*64+e], s);
        g_embW[blk*GG + g] = s;
    } else if (blk == NV) {
        for (int k = 0; k < HH; ++k) {
            float s = 0.f;
            for (int i = 0; i < 65; ++i) s = fmaf(wih0[g*65+i], wh2e[i*HH+k], s);
            g_W[k*GG + g] = s;                       // M transposed (k-major)
        }
        float s = 0.f;
        for (int i = 0; i < 65; ++i) s = fmaf(wih0[g*65+i], bh2e[i], s);
        g_base[g] = bih0[g] + s;
        g_w64[g]  = wih0[g*65 + 64];
    } else {
        int m = blk - NV - 1;   // 0..4
        const float* w = (m==0)?whh0 : (m==1)?wih1 : (m==2)?whh1 : (m==3)?wih2 : whh2;
        for (int k = 0; k < HH; ++k)
            g_W[(1+m)*WSLOT + k*GG + g] = w[g*HH + k];
    }
}

// -------- generic GRU layer (input & hidden are 32-dim, lane j owns index j) --------
__device__ __forceinline__ void gru_layer(
    const float* __restrict__ Wi, const float* __restrict__ Wh,
    float xv, float& h, int j,
    float bir, float biz, float bin, float bhr, float bhz, float bhn)
{
    float ar = bir, az = biz, an = bin;
    float br = bhr, bz = bhz, bn = bhn;
    #pragma unroll
    for (int k = 0; k < 32; ++k) {
        float xk = __shfl_sync(0xffffffffu, xv, k);
        float hk = __shfl_sync(0xffffffffu, h,  k);
        ar = fmaf(Wi[k*96 +      j], xk, ar);
        az = fmaf(Wi[k*96 + 32 + j], xk, az);
        an = fmaf(Wi[k*96 + 64 + j], xk, an);
        br = fmaf(Wh[k*96 +      j], hk, br);
        bz = fmaf(Wh[k*96 + 32 + j], hk, bz);
        bn = fmaf(Wh[k*96 + 64 + j], hk, bn);
    }
    float rg = sigf(ar + br);
    float zg = sigf(az + bz);
    float ng = tanh_f(an + rg*bn);
    h = fmaf(zg, h - ng, ng);    // (1-z)*n + z*h
}

// -------- kernel 2: wavefront GRU --------
// grid = 128 CTAs (one per row), 512 threads (16 warps, one per batch element).
// All CTAs co-resident (128 <= 148 SMs) -> flag-based wavefront is deadlock-free.
__global__ void __launch_bounds__(512, 1) wave_kernel(
    const int*   __restrict__ x,
    const float* __restrict__ bhh0, const float* __restrict__ bih1,
    const float* __restrict__ bhh1, const float* __restrict__ bih2,
    const float* __restrict__ bhh2)
{
    extern __shared__ float sm[];
    float* sW = sm;                // 6*3072 weights
    float* sv = sm + 6*WSLOT;      // 7*96 bias/const vectors
    int tid = threadIdx.x;
    for (int i = tid; i < 6*WSLOT; i += 512) sW[i] = g_W[i];
    if (tid < GG) {
        sv[tid]        = g_base[tid];
        sv[GG + tid]   = g_w64[tid];
        sv[2*GG + tid] = bhh0[tid];
        sv[3*GG + tid] = bih1[tid];
        sv[4*GG + tid] = bhh1[tid];
        sv[5*GG + tid] = bih2[tid];
        sv[6*GG + tid] = bhh2[tid];
    }
    __syncthreads();

    const int r = blockIdx.x;
    const int b = tid >> 5;
    const int j = tid & 31;

    const float* Mt  = sW;
    const float* Wh0 = sW + 1*WSLOT;
    const float* Wi1 = sW + 2*WSLOT;
    const float* Wh1 = sW + 3*WSLOT;
    const float* Wi2 = sW + 4*WSLOT;
    const float* Wh2 = sW + 5*WSLOT;

    const float rowpos = (float)r * (1.0f/64.0f) - 1.0f;
    const float c_r = fmaf(sv[GG +      j], rowpos, sv[     j]);
    const float c_z = fmaf(sv[GG + 32 + j], rowpos, sv[32 + j]);
    const float c_n = fmaf(sv[GG + 64 + j], rowpos, sv[64 + j]);
    const float bh0r = sv[2*GG+j], bh0z = sv[2*GG+32+j], bh0n = sv[2*GG+64+j];
    const float bi1r = sv[3*GG+j], bi1z = sv[3*GG+32+j], bi1n = sv[3*GG+64+j];
    const float bh1r = sv[4*GG+j], bh1z = sv[4*GG+32+j], bh1n = sv[4*GG+64+j];
    const float bi2r = sv[5*GG+j], bi2z = sv[5*GG+32+j], bi2n = sv[5*GG+64+j];
    const float bh2r = sv[6*GG+j], bh2z = sv[6*GG+32+j], bh2n = sv[6*GG+64+j];

    float h0 = 0.f, h1 = 0.f, h2 = 0.f;   // fresh per row (matches reference)

    const int*   xp    = x   + (b*RS + r)*TT;
    float*       outp  = g_h + (size_t)(b*RS + r)*TT*HH;
    const float* prevp = g_h + (size_t)(b*RS + ((r>0)?(r-1):0))*TT*HH;
    volatile int* pf   = (volatile int*)&g_prog[((r>0)?(r-1):0)*BB + b];
    volatile int* pub  = (volatile int*)&g_prog[r*BB + b];

    for (int t = 0; t < TT; ++t) {
        const int tok = xp[t];
        const float* ew = g_embW + tok*GG;
        float ar = c_r + ew[     j];
        float az = c_z + ew[32 + j];
        float an = c_n + ew[64 + j];
        float br = bh0r, bz = bh0z, bn = bh0n;

        if (r > 0) {
            while (*pf <= t) { }       // wait for prev row's step t
            __threadfence();
            float pv = __ldcg(&prevp[t*HH + j]);
            #pragma unroll
            for (int k = 0; k < 32; ++k) {
                float pk = __shfl_sync(0xffffffffu, pv, k);
                float hk = __shfl_sync(0xffffffffu, h0, k);
                ar = fmaf(Mt [k*96 +      j], pk, ar);
                az = fmaf(Mt [k*96 + 32 + j], pk, az);
                an = fmaf(Mt [k*96 + 64 + j], pk, an);
                br = fmaf(Wh0[k*96 +      j], hk, br);
                bz = fmaf(Wh0[k*96 + 32 + j], hk, bz);
                bn = fmaf(Wh0[k*96 + 64 + j], hk, bn);
            }
        } else {
            #pragma unroll
            for (int k = 0; k < 32; ++k) {
                float hk = __shfl_sync(0xffffffffu, h0, k);
                br = fmaf(Wh0[k*96 +      j], hk, br);
                bz = fmaf(Wh0[k*96 + 32 + j], hk, bz);
                bn = fmaf(Wh0[k*96 + 64 + j], hk, bn);
            }
        }
        {
            float rg = sigf(ar + br);
            float zg = sigf(az + bz);
            float ng = tanh_f(an + rg*bn);
            h0 = fmaf(zg, h0 - ng, ng);
        }
        gru_layer(Wi1, Wh1, h0, h1, j, bi1r, bi1z, bi1n, bh1r, bh1z, bh1n);
        gru_layer(Wi2, Wh2, h1, h2, j, bi2r, bi2z, bi2n, bh2r, bh2z, bh2n);

        // publish top-layer output + progress (release pattern)
        outp[t*HH + j] = h2;
        __threadfence();
        __syncwarp();
        if (j == 0) *pub = t + 1;
    }
}

// -------- kernel 3: output projection pred = out @ w_out^T + b_out --------
// warp handles 4 tokens; lane owns vocab columns v = lane + 32k (k<9, guarded)
__global__ void __launch_bounds__(256) proj_kernel(
    const float* __restrict__ wout,   // [258][32]
    const float* __restrict__ bout,   // [258]
    float* __restrict__ pred)         // [262144][258]
{
    __shared__ float ws[32][264];     // [h][v], padded row -> conflict-free
    __shared__ float bs[288];
    int tid = threadIdx.x;
    for (int i = tid; i < NV*HH; i += 256) {
        int v = i >> 5, h = i & 31;   // wout flat = v*32 + h
        ws[h][v] = wout[i];
    }
    for (int i = tid; i < NV; i += 256) bs[i] = bout[i];
    __syncthreads();

    int warp = tid >> 5, lane = tid & 31;
    int tok0 = (blockIdx.x*8 + warp) * 4;

    float hv[4];
    #pragma unroll
    for (int i = 0; i < 4; ++i) hv[i] = g_h[(size_t)(tok0+i)*HH + lane];

    float acc[4][9];
    #pragma unroll
    for (int k = 0; k < 9; ++k) {
        int v = lane + 32*k;
        float bb = (v < NV) ? bs[v] : 0.f;
        #pragma unroll
        for (int i = 0; i < 4; ++i) acc[i][k] = bb;
    }
    #pragma unroll 8
    for (int h = 0; h < 32; ++h) {
        float w[9];
        #pragma unroll
        for (int k = 0; k < 9; ++k) { int v = lane + 32*k; w[k] = (v < NV) ? ws[h][v] : 0.f; }
        #pragma unroll
        for (int i = 0; i < 4; ++i) {
            float hb = __shfl_sync(0xffffffffu, hv[i], h);
            #pragma unroll
            for (int k = 0; k < 9; ++k) acc[i][k] = fmaf(w[k], hb, acc[i][k]);
        }
    }
    #pragma unroll
    for (int i = 0; i < 4; ++i) {
        size_t base = (size_t)(tok0+i)*NV;
        #pragma unroll
        for (int k = 0; k < 9; ++k) { int v = lane + 32*k; if (v < NV) pred[base + v] = acc[i][k]; }
    }
}

// -------- launch --------
extern "C" void kernel_launch(void* const* d_in, const int* in_sizes, int n_in,
                              void* d_out, int out_size)
{
    const int*   x    = (const int*)  d_in[0];
    const float* emb  = (const float*)d_in[1];
    const float* wih0 = (const float*)d_in[2];
    const float* whh0 = (const float*)d_in[3];
    const float* bih0 = (const float*)d_in[4];
    const float* bhh0 = (const float*)d_in[5];
    const float* wih1 = (const float*)d_in[6];
    const float* whh1 = (const float*)d_in[7];
    const float* bih1 = (const float*)d_in[8];
    const float* bhh1 = (const float*)d_in[9];
    const float* wih2 = (const float*)d_in[10];
    const float* whh2 = (const float*)d_in[11];
    const float* bih2 = (const float*)d_in[12];
    const float* bhh2 = (const float*)d_in[13];
    const float* wh2e = (const float*)d_in[14];
    const float* bh2e = (const float*)d_in[15];
    const float* wout = (const float*)d_in[16];
    const float* bout = (const float*)d_in[17];
    float* pred = (float*)d_out;

    const int smem_bytes = (6*WSLOT + 7*GG) * (int)sizeof(float);   // 76416
    cudaFuncSetAttribute(wave_kernel, cudaFuncAttributeMaxDynamicSharedMemorySize, smem_bytes);

    zero_prog_kernel<<<8, 256>>>();
    precompute_kernel<<<NV + 6, GG>>>(emb, wih0, bih0, wh2e, bh2e,
                                      whh0, wih1, whh1, wih2, whh2);
    wave_kernel<<<RS, 512, smem_bytes>>>(x, bhh0, bih1, bhh1, bih2, bhh2);
    proj_kernel<<<NTOK/(8*4), 256>>>(wout, bout, pred);
}

// round 7
// speedup vs baseline: 1.9758x; 1.9758x over previous
#include <cuda_runtime.h>
#include <cstdint>

// Fixed shapes
#define BB    16
#define RS    128
#define TT    128
#define HH    32
#define GG    96
#define NV    258
#define NTOK  (BB*RS*TT)     // 262144
#define RPAD  36             // padded row length (floats) for weight rows
#define MSIZE (GG*RPAD)      // 3456 floats per matrix

// -------- device scratch --------
__device__ float g_embW[NV*GG];           // W_ih0[:, :64] @ embed^T -> [258][96]
__device__ float g_Wp[6*MSIZE];           // 6 matrices [96][36] row-major padded:
                                          // 0:M 1:Wh0 2:Wi1 3:Wh1 4:Wi2 5:Wh2
__device__ float g_base[GG];              // b_ih0 + Wih0 @ b_h2e
__device__ float g_w64[GG];               // Wih0[:,64]
__device__ float g_h[(size_t)NTOK*HH];    // top-layer outputs [B][R][T][H]
__device__ int   g_flag[RS*4];            // per (row, warp) progress

// -------- helpers --------
__device__ __forceinline__ float sigf(float x)   { return __fdividef(1.0f, 1.0f + __expf(-x)); }
__device__ __forceinline__ float tanh_f(float x) { return __fdividef(2.0f, 1.0f + __expf(-2.0f*x)) - 1.0f; }

__device__ __forceinline__ void st_release(int* p, int v) {
    asm volatile("st.release.gpu.global.s32 [%0], %1;" :: "l"(p), "r"(v) : "memory");
}
__device__ __forceinline__ int ld_acquire(const int* p) {
    int v;
    asm volatile("ld.acquire.gpu.global.s32 %0, [%1];" : "=r"(v) : "l"(p) : "memory");
    return v;
}

// -------- kernel 0: zero flags (every launch/replay) --------
__global__ void zero_flag_kernel() {
    int i = blockIdx.x*blockDim.x + threadIdx.x;
    if (i < RS*4) g_flag[i] = 0;
}

// -------- kernel 1: precompute folded weights --------
__global__ void precompute_kernel(
    const float* __restrict__ emb,   // [258][64]
    const float* __restrict__ wih0,  // [96][65]
    const float* __restrict__ bih0,  // [96]
    const float* __restrict__ wh2e,  // [65][32]
    const float* __restrict__ bh2e,  // [65]
    const float* __restrict__ whh0,  // [96][32]
    const float* __restrict__ wih1,  // [96][32]
    const float* __restrict__ whh1,
    const float* __restrict__ wih2,
    const float* __restrict__ whh2)
{
    int g = threadIdx.x;     // 0..95
    int blk = blockIdx.x;
    if (blk < NV) {
        float s = 0.f;
        #pragma unroll
        for (int e = 0; e < 64; ++e) s = fmaf(wih0[g*65+e], emb[blk*64+e], s);
        g_embW[blk*GG + g] = s;
    } else if (blk == NV) {
        for (int k = 0; k < HH; ++k) {
            float s = 0.f;
            for (int i = 0; i < 65; ++i) s = fmaf(wih0[g*65+i], wh2e[i*HH+k], s);
            g_Wp[g*RPAD + k] = s;            // M = Wih0[:, :65] @ Wh2e
        }
        float s = 0.f;
        for (int i = 0; i < 65; ++i) s = fmaf(wih0[g*65+i], bh2e[i], s);
        g_base[g] = bih0[g] + s;
        g_w64[g]  = wih0[g*65 + 64];
    } else {
        int m = blk - NV - 1;   // 0..4 -> Wh0, Wi1, Wh1, Wi2, Wh2
        const float* w = (m==0)?whh0 : (m==1)?wih1 : (m==2)?whh1 : (m==3)?wih2 : whh2;
        for (int k = 0; k < HH; ++k)
            g_Wp[(1+m)*MSIZE + g*RPAD + k] = w[g*HH + k];
    }
}

// -------- matvec macros (4 batches, lane j owns hidden unit j) --------
#define A4(p0,p1,p2,p3, wv, s0,s1,s2,s3) \
    p0 = fmaf(wv, s0, p0); p1 = fmaf(wv, s1, p1); p2 = fmaf(wv, s2, p2); p3 = fmaf(wv, s3, p3);

#define KO(c, X0,X1,X2,X3, Y0,Y1,Y2,Y3) \
    A4(aR0,aR1,aR2,aR3, wir.c, X0,X1,X2,X3) A4(aR0,aR1,aR2,aR3, whr.c, Y0,Y1,Y2,Y3) \
    A4(aZ0,aZ1,aZ2,aZ3, wiz.c, X0,X1,X2,X3) A4(aZ0,aZ1,aZ2,aZ3, whz.c, Y0,Y1,Y2,Y3) \
    A4(aN0,aN1,aN2,aN3, win.c, X0,X1,X2,X3) A4(aM0,aM1,aM2,aM3, whn.c, Y0,Y1,Y2,Y3)

// WI/WH: float* matrix bases (smem); XP/HP: float2* stage arrays [2][32]
#define MLOOP(WI, WH, XP, HP) { \
    const float4* X4 = (const float4*)(XP); const float4* H4 = (const float4*)(HP); \
    _Pragma("unroll") \
    for (int kq = 0; kq < 8; ++kq) { \
        float4 wir = *(const float4*)((WI) + rowR + kq*4); \
        float4 wiz = *(const float4*)((WI) + rowZ + kq*4); \
        float4 win = *(const float4*)((WI) + rowN + kq*4); \
        float4 whr = *(const float4*)((WH) + rowR + kq*4); \
        float4 whz = *(const float4*)((WH) + rowZ + kq*4); \
        float4 whn = *(const float4*)((WH) + rowN + kq*4); \
        float4 xa = X4[2*kq], xb = X4[2*kq+1], xc = X4[16+2*kq], xd = X4[16+2*kq+1]; \
        float4 ha = H4[2*kq], hb = H4[2*kq+1], hc = H4[16+2*kq], hd = H4[16+2*kq+1]; \
        KO(x, xa.x,xa.y,xc.x,xc.y, ha.x,ha.y,hc.x,hc.y) \
        KO(y, xa.z,xa.w,xc.z,xc.w, ha.z,ha.w,hc.z,hc.w) \
        KO(z, xb.x,xb.y,xd.x,xd.y, hb.x,hb.y,hd.x,hd.y) \
        KO(w, xb.z,xb.w,xd.z,xd.w, hb.z,hb.w,hd.z,hd.w) \
    } }

#define GRUUP(h, aR, aZ, aNi, aNh) { \
    float rg = sigf(aR); float zg = sigf(aZ); \
    float ng = tanh_f(aNi + rg*(aNh)); \
    h = fmaf(zg, (h) - ng, ng); }

// -------- kernel 2: wavefront GRU --------
// grid = 128 CTAs (one per row), 128 threads = 4 warps, warp w owns batches 4w..4w+3.
// Warps fully independent; cross-row sync via per-(row,warp) release/acquire flags.
__global__ void __launch_bounds__(128, 1) wave_kernel(
    const int*   __restrict__ x,
    const float* __restrict__ bhh0, const float* __restrict__ bih1,
    const float* __restrict__ bhh1, const float* __restrict__ bih2,
    const float* __restrict__ bhh2)
{
    extern __shared__ float sm[];
    float*  sW   = sm;                              // 6*MSIZE floats (82944 B)
    float2* stg  = (float2*)(sm + 6*MSIZE);         // 4 warps * 4 vecs * 2 ps * 32
    int*    stok = (int*)(sm + 6*MSIZE + 2048);     // 16*128 tokens

    const int tid = threadIdx.x;
    const int r   = blockIdx.x;
    const int w   = tid >> 5;
    const int j   = tid & 31;

    {   // stage weights, zero stages, stage tokens
        const float4* src = (const float4*)g_Wp;
        float4* dst = (float4*)sW;
        for (int i = tid; i < 6*MSIZE/4; i += 128) dst[i] = src[i];
        for (int i = tid; i < 4*4*2*32; i += 128) stg[i] = make_float2(0.f, 0.f);
        for (int i = tid; i < BB*TT; i += 128) {
            int b = i >> 7, tt = i & 127;
            stok[i] = x[(b*RS + r)*TT + tt];
        }
    }
    __syncthreads();

    const int rowR = j*RPAD, rowZ = (32+j)*RPAD, rowN = (64+j)*RPAD;
    const float* W_M  = sW;
    const float* W_h0 = sW + 1*MSIZE;
    const float* W_i1 = sW + 2*MSIZE;
    const float* W_h1 = sW + 3*MSIZE;
    const float* W_i2 = sW + 4*MSIZE;
    const float* W_h2 = sW + 5*MSIZE;

    float2* S_pv = stg + (w*4 + 0)*64;    // [ps*32 + k]
    float2* S_x1 = stg + (w*4 + 1)*64;    // h0 (layer1 input / layer0 hidden)
    float2* S_x2 = stg + (w*4 + 2)*64;    // h1
    float2* S_h2 = stg + (w*4 + 3)*64;    // h2

    const float rowpos = (float)r * (1.0f/64.0f) - 1.0f;
    const float K0r  = g_base[j]    + g_w64[j]   *rowpos + bhh0[j];
    const float K0z  = g_base[32+j] + g_w64[32+j]*rowpos + bhh0[32+j];
    const float K0ni = g_base[64+j] + g_w64[64+j]*rowpos;
    const float K0nh = bhh0[64+j];
    const float K1r  = bih1[j] + bhh1[j];
    const float K1z  = bih1[32+j] + bhh1[32+j];
    const float K1ni = bih1[64+j];
    const float K1nh = bhh1[64+j];
    const float K2r  = bih2[j] + bhh2[j];
    const float K2z  = bih2[32+j] + bhh2[32+j];
    const float K2ni = bih2[64+j];
    const float K2nh = bhh2[64+j];

    const int b0 = w*4;
    float* out0 = g_h + (size_t)((b0+0)*RS + r)*TT*HH;
    float* out1 = g_h + (size_t)((b0+1)*RS + r)*TT*HH;
    float* out2 = g_h + (size_t)((b0+2)*RS + r)*TT*HH;
    float* out3 = g_h + (size_t)((b0+3)*RS + r)*TT*HH;
    const int rp = (r > 0) ? (r-1) : 0;
    const float* pr0 = g_h + (size_t)((b0+0)*RS + rp)*TT*HH;
    const float* pr1 = g_h + (size_t)((b0+1)*RS + rp)*TT*HH;
    const float* pr2 = g_h + (size_t)((b0+2)*RS + rp)*TT*HH;
    const float* pr3 = g_h + (size_t)((b0+3)*RS + rp)*TT*HH;
    int*       pub = &g_flag[r*4 + w];
    const int* pf  = &g_flag[rp*4 + w];

    float h0_0=0.f,h0_1=0.f,h0_2=0.f,h0_3=0.f;
    float h1_0=0.f,h1_1=0.f,h1_2=0.f,h1_3=0.f;
    float h2_0=0.f,h2_1=0.f,h2_2=0.f,h2_3=0.f;

    for (int t = 0; t < TT; ++t) {
        // issue token/embW loads early (hidden behind wait + matvecs)
        const int tk0 = stok[(b0+0)*TT + t];
        const int tk1 = stok[(b0+1)*TT + t];
        const int tk2 = stok[(b0+2)*TT + t];
        const int tk3 = stok[(b0+3)*TT + t];
        const float* e0 = g_embW + tk0*GG;
        const float* e1 = g_embW + tk1*GG;
        const float* e2 = g_embW + tk2*GG;
        const float* e3 = g_embW + tk3*GG;
        float er0 = e0[j],    er1 = e1[j],    er2 = e2[j],    er3 = e3[j];
        float ez0 = e0[32+j], ez1 = e1[32+j], ez2 = e2[32+j], ez3 = e3[32+j];
        float en0 = e0[64+j], en1 = e1[64+j], en2 = e2[64+j], en3 = e3[64+j];

        if (r > 0) {
            while (ld_acquire(pf) <= t) { }
            float p0 = __ldcg(pr0 + t*HH + j);
            float p1 = __ldcg(pr1 + t*HH + j);
            float p2 = __ldcg(pr2 + t*HH + j);
            float p3 = __ldcg(pr3 + t*HH + j);
            S_pv[j]    = make_float2(p0, p1);
            S_pv[32+j] = make_float2(p2, p3);
        }
        __syncwarp();

        // ---- layer 0: x-side = embW + M@pv, h-side = Wh0@h0 ----
        float aR0=K0r+er0, aR1=K0r+er1, aR2=K0r+er2, aR3=K0r+er3;
        float aZ0=K0z+ez0, aZ1=K0z+ez1, aZ2=K0z+ez2, aZ3=K0z+ez3;
        float aN0=K0ni+en0, aN1=K0ni+en1, aN2=K0ni+en2, aN3=K0ni+en3;
        float aM0=K0nh, aM1=K0nh, aM2=K0nh, aM3=K0nh;
        MLOOP(W_M, W_h0, S_pv, S_x1)
        GRUUP(h0_0, aR0, aZ0, aN0, aM0)
        GRUUP(h0_1, aR1, aZ1, aN1, aM1)
        GRUUP(h0_2, aR2, aZ2, aN2, aM2)
        GRUUP(h0_3, aR3, aZ3, aN3, aM3)
        __syncwarp();
        S_x1[j]    = make_float2(h0_0, h0_1);
        S_x1[32+j] = make_float2(h0_2, h0_3);
        __syncwarp();

        // ---- layer 1 ----
        aR0=K1r; aR1=K1r; aR2=K1r; aR3=K1r;
        aZ0=K1z; aZ1=K1z; aZ2=K1z; aZ3=K1z;
        aN0=K1ni; aN1=K1ni; aN2=K1ni; aN3=K1ni;
        aM0=K1nh; aM1=K1nh; aM2=K1nh; aM3=K1nh;
        MLOOP(W_i1, W_h1, S_x1, S_x2)
        GRUUP(h1_0, aR0, aZ0, aN0, aM0)
        GRUUP(h1_1, aR1, aZ1, aN1, aM1)
        GRUUP(h1_2, aR2, aZ2, aN2, aM2)
        GRUUP(h1_3, aR3, aZ3, aN3, aM3)
        __syncwarp();
        S_x2[j]    = make_float2(h1_0, h1_1);
        S_x2[32+j] = make_float2(h1_2, h1_3);
        __syncwarp();

        // ---- layer 2 ----
        aR0=K2r; aR1=K2r; aR2=K2r; aR3=K2r;
        aZ0=K2z; aZ1=K2z; aZ2=K2z; aZ3=K2z;
        aN0=K2ni; aN1=K2ni; aN2=K2ni; aN3=K2ni;
        aM0=K2nh; aM1=K2nh; aM2=K2nh; aM3=K2nh;
        MLOOP(W_i2, W_h2, S_x2, S_h2)
        GRUUP(h2_0, aR0, aZ0, aN0, aM0)
        GRUUP(h2_1, aR1, aZ1, aN1, aM1)
        GRUUP(h2_2, aR2, aZ2, aN2, aM2)
        GRUUP(h2_3, aR3, aZ3, aN3, aM3)
        __syncwarp();
        S_h2[j]    = make_float2(h2_0, h2_1);
        S_h2[32+j] = make_float2(h2_2, h2_3);

        // publish top-layer output + flag (release)
        out0[t*HH + j] = h2_0;
        out1[t*HH + j] = h2_1;
        out2[t*HH + j] = h2_2;
        out3[t*HH + j] = h2_3;
        __syncwarp();
        if (j == 0) st_release(pub, t + 1);
    }
}

// -------- kernel 3: output projection (8 tokens per warp) --------
__global__ void __launch_bounds__(256) proj_kernel(
    const float* __restrict__ wout,   // [258][32]
    const float* __restrict__ bout,   // [258]
    float* __restrict__ pred)         // [262144][258]
{
    __shared__ float ws[32][264];
    __shared__ float bs[288];
    int tid = threadIdx.x;
    for (int i = tid; i < NV*HH; i += 256) {
        int v = i >> 5, h = i & 31;
        ws[h][v] = wout[i];
    }
    for (int i = tid; i < NV; i += 256) bs[i] = bout[i];
    __syncthreads();

    int warp = tid >> 5, lane = tid & 31;
    int tok0 = (blockIdx.x*8 + warp) * 8;

    float hv[8];
    #pragma unroll
    for (int i = 0; i < 8; ++i) hv[i] = g_h[(size_t)(tok0+i)*HH + lane];

    float acc[8][9];
    #pragma unroll
    for (int k = 0; k < 9; ++k) {
        int v = lane + 32*k;
        float b = (v < NV) ? bs[v] : 0.f;
        #pragma unroll
        for (int i = 0; i < 8; ++i) acc[i][k] = b;
    }
    #pragma unroll 4
    for (int h = 0; h < 32; ++h) {
        float wv[9];
        #pragma unroll
        for (int k = 0; k < 9; ++k) { int v = lane + 32*k; wv[k] = (v < NV) ? ws[h][v] : 0.f; }
        #pragma unroll
        for (int i = 0; i < 8; ++i) {
            float hb = __shfl_sync(0xffffffffu, hv[i], h);
            #pragma unroll
            for (int k = 0; k < 9; ++k) acc[i][k] = fmaf(wv[k], hb, acc[i][k]);
        }
    }
    #pragma unroll
    for (int i = 0; i < 8; ++i) {
        size_t base = (size_t)(tok0+i)*NV;
        #pragma unroll
        for (int k = 0; k < 9; ++k) { int v = lane + 32*k; if (v < NV) pred[base + v] = acc[i][k]; }
    }
}

// -------- launch --------
extern "C" void kernel_launch(void* const* d_in, const int* in_sizes, int n_in,
                              void* d_out, int out_size)
{
    const int*   x    = (const int*)  d_in[0];
    const float* emb  = (const float*)d_in[1];
    const float* wih0 = (const float*)d_in[2];
    const float* whh0 = (const float*)d_in[3];
    const float* bih0 = (const float*)d_in[4];
    const float* bhh0 = (const float*)d_in[5];
    const float* wih1 = (const float*)d_in[6];
    const float* whh1 = (const float*)d_in[7];
    const float* bih1 = (const float*)d_in[8];
    const float* bhh1 = (const float*)d_in[9];
    const float* wih2 = (const float*)d_in[10];
    const float* whh2 = (const float*)d_in[11];
    const float* bih2 = (const float*)d_in[12];
    const float* bhh2 = (const float*)d_in[13];
    const float* wh2e = (const float*)d_in[14];
    const float* bh2e = (const float*)d_in[15];
    const float* wout = (const float*)d_in[16];
    const float* bout = (const float*)d_in[17];
    float* pred = (float*)d_out;

    // smem: weights 82944 B + stages 8192 B + tokens 8192 B = 99328 B
    const int smem_bytes = (6*MSIZE + 2048 + 2048) * (int)sizeof(float);
    cudaFuncSetAttribute(wave_kernel, cudaFuncAttributeMaxDynamicSharedMemorySize, smem_bytes);

    zero_flag_kernel<<<2, 256>>>();
    precompute_kernel<<<NV + 6, GG>>>(emb, wih0, bih0, wh2e, bh2e,
                                      whh0, wih1, whh1, wih2, whh2);
    wave_kernel<<<RS, 128, smem_bytes>>>(x, bhh0, bih1, bhh1, bih2, bhh2);
    proj_kernel<<<NTOK/64, 256>>>(wout, bout, pred);
}